// round 6
// baseline (speedup 1.0000x reference)
#include <cuda_runtime.h>

#define B 32
#define S 1024
#define W 512
#define D 768
#define NPOS 32
#define NT 192           // = D/4 threads, one float4 column per thread
#define TOTW (B * W)     // 16384 words
#define NBLK 1480        // single persistent wave
#define MAXIT 12         // ceil(TOTW / NBLK)

__global__ void __launch_bounds__(NT) charpool_dual_kernel(
    const float* __restrict__ feats,      // [B, S, D]
    const int* __restrict__ word_lens,    // [B, W]
    const int* __restrict__ seq_len,      // [B]
    const int* __restrict__ pos,          // [B, W]
    const float* __restrict__ pos_table,  // [NPOS, D]
    float* __restrict__ out)              // [B, W, D]
{
    __shared__ int s_start[MAXIT];
    __shared__ int s_len[MAXIT];
    __shared__ int s_p[MAXIT];
    __shared__ int s_valid[MAXIT];

    const int bid = blockIdx.x;
    const int t = threadIdx.x;
    const float4* __restrict__ ptab = reinterpret_cast<const float4*>(pos_table);

    // number of words this CTA owns (ids: bid, bid+NBLK, ...)
    const int n = (TOTW - 1 - bid) / NBLK + 1;

    // preamble: threads 0..n-1 each resolve one word's metadata into smem
    if (t < n) {
        const int id = bid + t * NBLK;
        const int w  = id & (W - 1);
        const int b  = id >> 9;
        const int start = __ldg(&word_lens[id]);
        const int nxt   = (w + 1 < W) ? __ldg(&word_lens[id + 1]) : 0;
        const int end   = (nxt == 0) ? __ldg(&seq_len[b]) : nxt;
        int len = end - start;
        if (len < 1) len = 1;
        s_start[t] = start;
        s_len[t]   = len;
        s_p[t]     = __ldg(&pos[id]);
        s_valid[t] = (start != 0) || (w == 0);
    }
    __syncthreads();

    const int dq = D / 4;

    for (int k = 0; k < n; k += 2) {
        const bool has2 = (k + 1 < n);

        const int idA = bid + k * NBLK;
        const int stA = s_start[k], lnA = s_len[k];
        const int pA  = s_p[k],     vA  = s_valid[k];

        int idB = 0, stB = 0, lnB = 1, pB = 0, vB = 0;
        if (has2) {
            idB = idA + NBLK;
            stB = s_start[k + 1]; lnB = s_len[k + 1];
            pB  = s_p[k + 1];     vB  = s_valid[k + 1];
        }

        const float4* fpA = reinterpret_cast<const float4*>(
            feats + ((size_t)(idA >> 9) * S + (size_t)stA) * D) + t;
        const float4* fpB = reinterpret_cast<const float4*>(
            feats + ((size_t)(idB >> 9) * S + (size_t)stB) * D) + t;

        const int lA = vA ? lnA : 0;          // invalid words: no char loads
        const int lB = vB ? lnB : 0;
        const int smax = (lA > lB) ? lA : lB;

        float4 accA = make_float4(0.f, 0.f, 0.f, 0.f);
        float4 accB = make_float4(0.f, 0.f, 0.f, 0.f);
        const float4 z = make_float4(0.f, 0.f, 0.f, 0.f);

        for (int s = 0; s < smax; s += 4) {
            // 8 independent row loads (4 per word) issued before any consume
            float4 a0 = (s     < lA) ? fpA[0 * dq] : z;
            float4 a1 = (s + 1 < lA) ? fpA[1 * dq] : z;
            float4 a2 = (s + 2 < lA) ? fpA[2 * dq] : z;
            float4 a3 = (s + 3 < lA) ? fpA[3 * dq] : z;
            float4 b0 = (s     < lB) ? fpB[0 * dq] : z;
            float4 b1 = (s + 1 < lB) ? fpB[1 * dq] : z;
            float4 b2 = (s + 2 < lB) ? fpB[2 * dq] : z;
            float4 b3 = (s + 3 < lB) ? fpB[3 * dq] : z;

            accA.x += (a0.x + a1.x) + (a2.x + a3.x);
            accA.y += (a0.y + a1.y) + (a2.y + a3.y);
            accA.z += (a0.z + a1.z) + (a2.z + a3.z);
            accA.w += (a0.w + a1.w) + (a2.w + a3.w);
            accB.x += (b0.x + b1.x) + (b2.x + b3.x);
            accB.y += (b0.y + b1.y) + (b2.y + b3.y);
            accB.z += (b0.z + b1.z) + (b2.z + b3.z);
            accB.w += (b0.w + b1.w) + (b2.w + b3.w);

            fpA += 4 * dq;
            fpB += 4 * dq;
        }

        // finalize A
        {
            const float4 pt = ptab[pA * dq + t];
            float4 r;
            if (vA) {
                const float inv = 1.0f / (float)lnA;
                r.x = fmaf(accA.x, inv, pt.x);
                r.y = fmaf(accA.y, inv, pt.y);
                r.z = fmaf(accA.z, inv, pt.z);
                r.w = fmaf(accA.w, inv, pt.w);
            } else {
                r = pt;   // pos=0 table row is zero
            }
            __stcs(reinterpret_cast<float4*>(out + (size_t)idA * D) + t, r);
        }
        // finalize B
        if (has2) {
            const float4 pt = ptab[pB * dq + t];
            float4 r;
            if (vB) {
                const float inv = 1.0f / (float)lnB;
                r.x = fmaf(accB.x, inv, pt.x);
                r.y = fmaf(accB.y, inv, pt.y);
                r.z = fmaf(accB.z, inv, pt.z);
                r.w = fmaf(accB.w, inv, pt.w);
            } else {
                r = pt;
            }
            __stcs(reinterpret_cast<float4*>(out + (size_t)idB * D) + t, r);
        }
    }
}

extern "C" void kernel_launch(void* const* d_in, const int* in_sizes, int n_in,
                              void* d_out, int out_size)
{
    const float* feats     = (const float*)d_in[0];
    const int*   word_lens = (const int*)d_in[1];
    const int*   seq_len   = (const int*)d_in[2];
    const int*   pos       = (const int*)d_in[3];
    const float* pos_table = (const float*)d_in[4];
    float* out = (float*)d_out;

    charpool_dual_kernel<<<NBLK, NT>>>(feats, word_lens, seq_len, pos, pos_table, out);
}